// round 8
// baseline (speedup 1.0000x reference)
#include <cuda_runtime.h>
#include <cstdint>
#include <math_constants.h>

#define N_SPLINES 64
#define C_DIM     64
#define T_DIM     68
#define NJ        67
#define NTH       (2*NJ)      // 134 raw thresholds per spline
#define NPF       (NTH + 1)   // 135 prefix polys (worst case, no dedup)
#define NB        512         // buckets, width 1/64 over [-4,4)
#define NTHP      140         // padded distinct-threshold array

// Precomputed per-spline tables (dedup'd)
// g_th layout: [0] = -INF, [1..D] = distinct sorted thresholds, [D+1..139] = +INF
__device__ float   g_th[N_SPLINES][NTHP];
__device__ float4  g_C [N_SPLINES][NPF];     // Taylor coeffs of prefix poly m (0..D)
__device__ uint8_t g_bt[N_SPLINES][NB];      // bucket -> #{distinct th < edge_b}; bt[0]=0

// ---------------------------------------------------------------------------
// Precompute (fp64): Cox-de Boor -> per-interval cubics -> threshold
// decomposition -> sort -> prefix polys -> DEDUP -> Taylor-center -> buckets.
// ---------------------------------------------------------------------------
__device__ __forceinline__ double sinv(double den) {
    return den == 0.0 ? 0.0 : 1.0 / den;
}

__device__ __forceinline__ void build_p3(const double* st, int i, double p3[4][4]) {
    double p1[3][2][2];
#pragma unroll
    for (int a2 = 0; a2 < 3; ++a2) {
        int a = i + a2;
        double invA = sinv(st[a + 1] - st[a]);
        double invB = sinv(st[a + 2] - st[a + 1]);
        p1[a2][0][0] = -st[a] * invA;
        p1[a2][0][1] = invA;
        p1[a2][1][0] = st[a + 2] * invB;
        p1[a2][1][1] = -invB;
    }
    double p2[2][3][3];
#pragma unroll
    for (int a2 = 0; a2 < 2; ++a2) {
        int a = i + a2;
#pragma unroll
        for (int jj = 0; jj < 3; ++jj)
#pragma unroll
            for (int d = 0; d < 3; ++d) p2[a2][jj][d] = 0.0;
        double invA = sinv(st[a + 2] - st[a]);
        double invB = sinv(st[a + 3] - st[a + 1]);
        double l0 = -st[a] * invA, l1 = invA;
        double r0 = st[a + 3] * invB, r1 = -invB;
#pragma unroll
        for (int jj = 0; jj < 2; ++jj)
#pragma unroll
            for (int d = 0; d < 2; ++d) {
                p2[a2][jj][d]     += l0 * p1[a2][jj][d];
                p2[a2][jj][d + 1] += l1 * p1[a2][jj][d];
            }
#pragma unroll
        for (int jj = 1; jj < 3; ++jj)
#pragma unroll
            for (int d = 0; d < 2; ++d) {
                p2[a2][jj][d]     += r0 * p1[a2 + 1][jj - 1][d];
                p2[a2][jj][d + 1] += r1 * p1[a2 + 1][jj - 1][d];
            }
    }
#pragma unroll
    for (int jj = 0; jj < 4; ++jj)
#pragma unroll
        for (int d = 0; d < 4; ++d) p3[jj][d] = 0.0;
    {
        int a = i;
        double invA = sinv(st[a + 3] - st[a]);
        double invB = sinv(st[a + 4] - st[a + 1]);
        double l0 = -st[a] * invA, l1 = invA;
        double r0 = st[a + 4] * invB, r1 = -invB;
#pragma unroll
        for (int jj = 0; jj < 3; ++jj)
#pragma unroll
            for (int d = 0; d < 3; ++d) {
                p3[jj][d]     += l0 * p2[0][jj][d];
                p3[jj][d + 1] += l1 * p2[0][jj][d];
            }
#pragma unroll
        for (int jj = 1; jj < 4; ++jj)
#pragma unroll
            for (int d = 0; d < 3; ++d) {
                p3[jj][d]     += r0 * p2[1][jj - 1][d];
                p3[jj][d + 1] += r1 * p2[1][jj - 1][d];
            }
    }
}

__global__ void precompute_kernel(const float* __restrict__ t,
                                  const float* __restrict__ c) {
    const int s   = blockIdx.x;
    const int tid = threadIdx.x;

    __shared__ double st[T_DIM];
    __shared__ double sc[C_DIM];
    __shared__ double sP[C_DIM][4][4];
    __shared__ double qm[NJ][4];
    __shared__ float  thr[NTH];
    __shared__ float  sth[NTH];
    __shared__ int    sidx[NTH];
    __shared__ double sv[NTH][4];
    __shared__ float  dval[NTH];
    __shared__ int    dmap[NTH];
    __shared__ int    dcnt;

    if (tid < T_DIM) st[tid] = (double)t[s * T_DIM + tid];
    if (tid < C_DIM) sc[tid] = (double)c[s * C_DIM + tid];
    __syncthreads();

    // A1: thread i builds p3(i)
    if (tid < C_DIM) {
        double p3[4][4];
        build_p3(st, tid, p3);
#pragma unroll
        for (int jj = 0; jj < 4; ++jj)
#pragma unroll
            for (int d = 0; d < 4; ++d) sP[tid][jj][d] = p3[jj][d];
    }
    __syncthreads();

    // A2: thread j combines pieces -> monomial Q_j
    if (tid < NJ) {
        int j = tid;
        double bb[4] = {0.0, 0.0, 0.0, 0.0};
        int ilo = (j - 3 < 0) ? 0 : j - 3;
        int ihi = (j < C_DIM - 1) ? j : C_DIM - 1;
        for (int i = ilo; i <= ihi; ++i) {
            int jj = j - i;
            double ci = sc[i];
#pragma unroll
            for (int d = 0; d < 4; ++d) bb[d] += ci * sP[i][jj][d];
        }
#pragma unroll
        for (int d = 0; d < 4; ++d) qm[j][d] = bb[d];
    }

    // B: raw thresholds
    if (tid < NTH) {
        if (tid < NJ) thr[tid] = t[s * T_DIM + tid];
        else {
            int j = tid - NJ;
            thr[tid] = fmaxf(t[s * T_DIM + j], t[s * T_DIM + j + 1]);
        }
    }
    __syncthreads();

    // C: rank sort (stable)
    if (tid < NTH) {
        float v = thr[tid];
        int r = 0;
        for (int i = 0; i < NTH; ++i) {
            float w = thr[i];
            r += (w < v) || (w == v && i < tid);
        }
        sth[r] = v;
        sidx[r] = tid;
    }
    __syncthreads();

    // D: signed pieces, inclusive scan (prefix polys over raw sorted order)
    if (tid < NTH) {
        int k = sidx[tid];
        int p = (k < NJ) ? k : k - NJ;
        double sgn = (k < NJ) ? 1.0 : -1.0;
#pragma unroll
        for (int d = 0; d < 4; ++d) sv[tid][d] = sgn * qm[p][d];
    }
    __syncthreads();
    for (int stp = 1; stp < NTH; stp <<= 1) {
        double tmp[4] = {0.0, 0.0, 0.0, 0.0};
        bool act = (tid < NTH) && (tid >= stp);
        if (act) {
#pragma unroll
            for (int d = 0; d < 4; ++d) tmp[d] = sv[tid - stp][d];
        }
        __syncthreads();
        if (act) {
#pragma unroll
            for (int d = 0; d < 4; ++d) sv[tid][d] += tmp[d];
        }
        __syncthreads();
    }

    // D2: deduplicate — keep prefix AFTER the last copy of each distinct value
    if (tid == 0) {
        int d = 0;
        for (int i = 0; i < NTH; ++i) {
            if (i == NTH - 1 || sth[i + 1] != sth[i]) {
                dval[d] = sth[i];
                dmap[d] = i;
                ++d;
            }
        }
        dcnt = d;
    }
    __syncthreads();
    const int D = dcnt;

    // E: Taylor-center prefix poly m (1..D) at dval[m-1]; zero elsewhere
    if (tid <= NTH) {
        int m = tid;
        float4 oc = make_float4(0.f, 0.f, 0.f, 0.f);
        if (m > 0 && m <= D) {
            double bb[4];
#pragma unroll
            for (int d = 0; d < 4; ++d) bb[d] = sv[dmap[m - 1]][d];
            double tc = (double)dval[m - 1];
#pragma unroll
            for (int pass = 0; pass < 3; ++pass)
#pragma unroll
                for (int d = 2; d >= 0; --d)
                    if (d >= pass) bb[d] += tc * bb[d + 1];
            oc = make_float4((float)bb[0], (float)bb[1], (float)bb[2], (float)bb[3]);
        }
        g_C[s][m] = oc;
    }
    // F: padded distinct thresholds
    if (tid < NTHP - 1) {
        g_th[s][tid + 1] = (tid < D) ? dval[tid] : CUDART_INF_F;
    }
    if (tid == 0) g_th[s][0] = -CUDART_INF_F;

    // G: bucket table bt[b] = #{distinct th < edge_b}; edge_0 = -INF
    for (int b = tid; b < NB; b += blockDim.x) {
        int cnt = 0;
        if (b > 0) {
            float edge = -4.0f + (float)b * (1.0f / 64.0f);   // exact in fp32
            for (int i = 0; i < D; ++i) cnt += (dval[i] < edge);
        }
        g_bt[s][b] = (uint8_t)cnt;
    }
}

// ---------------------------------------------------------------------------
// Main kernel: branchless bucket + 5 probes; per-lane bad-bitmask; single
// cold fixup block after the row loop guarantees exactness.
// ---------------------------------------------------------------------------
#define TH_STRIDE 141   // floats per spline (140 used), 141%32=13 coprime
#define C_STRIDE  137   // float4 per spline (135 used), odd
#define BT_WORDS  129   // words per spline bucket row (128 used), odd

extern __shared__ float dynsmem[];

__global__ __launch_bounds__(1024, 2)
void bspline_main_kernel(const float* __restrict__ x,
                         float* __restrict__ out, int B) {
    float*    sTh = dynsmem;                                  // 32*141 floats
    float4*   sC  = (float4*)(dynsmem + 32 * TH_STRIDE + 12); // 16B aligned
    uint32_t* sBt = (uint32_t*)(sC + 32 * C_STRIDE);          // 32*129 words

    const int tid   = threadIdx.x;
    const int sBase = blockIdx.y * 32;

    for (int i = tid; i < 32 * NTHP; i += 1024) {
        int sp = i / NTHP, k = i - sp * NTHP;
        sTh[sp * TH_STRIDE + k] = g_th[sBase + sp][k];
    }
    for (int i = tid; i < 32 * NPF; i += 1024) {
        int sp = i / NPF, k = i - sp * NPF;
        sC[sp * C_STRIDE + k] = g_C[sBase + sp][k];
    }
    for (int i = tid; i < 32 * (NB / 4); i += 1024) {
        int sp = i >> 7, k = i & 127;
        sBt[sp * BT_WORDS + k] = ((const uint32_t*)g_bt[sBase + sp])[k];
    }
    __syncthreads();

    const int lane = tid & 31;
    const int warp = tid >> 5;
    const float*   tbv = &sTh[lane * TH_STRIDE];   // tbv[m]: sentinel-padded distinct th
    const float4*  cb  = &sC[lane * C_STRIDE];
    const uint8_t* btb = (const uint8_t*)&sBt[lane * BT_WORDS];
    const int col = sBase + lane;
    const int wstride = gridDim.x * 32;

    const int rstart = blockIdx.x * 32 + warp;
    int row = rstart;
    unsigned badmask = 0;
    int iter = 0;
    float xv = x[row * N_SPLINES + col];

    while (true) {
        const int  nrow = row + wstride;
        const bool more = (nrow < B);
        float xn = 0.0f;
        if (more) xn = x[nrow * N_SPLINES + col];          // prefetch next row

        int b = __float2int_rz(fmaf(xv, 64.0f, 256.0f));   // (x+4)*64
        b = min(max(b, 0), NB - 1);
        const int m0 = (int)btb[b];

        const float q0 = tbv[m0];
        const float q1 = tbv[m0 + 1];
        const float q2 = tbv[m0 + 2];
        const float q3 = tbv[m0 + 3];
        const float q4 = tbv[m0 + 4];

        const int cnt = (q1 <= xv) + (q2 <= xv) + (q3 <= xv);
        const bool bad = (q0 > xv) | (q4 <= xv);
        const int m = m0 + cnt;

        const float  v   = tbv[m];
        const float  ctr = (m > 0) ? v : 0.0f;             // m=0 poly is zero
        const float4 cf  = cb[m];
        const float  u   = xv - ctr;
        out[row * N_SPLINES + col] =
            fmaf(fmaf(fmaf(cf.w, u, cf.z), u, cf.y), u, cf.x);

        badmask |= (bad ? 1u : 0u) << iter;

        if (!more) break;
        row = nrow; xv = xn; ++iter;
    }

    // Cold exact fixup for flagged rows (expected ~3% of warps, ~1 row each)
    if (badmask) {
        while (badmask) {
            const int i = __ffs(badmask) - 1;
            badmask &= badmask - 1;
            const int r = rstart + i * wstride;
            const float xw = x[r * N_SPLINES + col];

            int b = __float2int_rz(fmaf(xw, 64.0f, 256.0f));
            b = min(max(b, 0), NB - 1);
            int m = (int)btb[b];
            while (tbv[m] > xw) --m;          // -INF sentinel terminates
            while (tbv[m + 1] <= xw) ++m;     // +INF sentinels terminate

            const float  vv  = tbv[m];
            const float  ctr = (m > 0) ? vv : 0.0f;
            const float4 cf  = cb[m];
            const float  u   = xw - ctr;
            out[r * N_SPLINES + col] =
                fmaf(fmaf(fmaf(cf.w, u, cf.z), u, cf.y), u, cf.x);
        }
    }
}

// ---------------------------------------------------------------------------
extern "C" void kernel_launch(void* const* d_in, const int* in_sizes, int n_in,
                              void* d_out, int out_size) {
    const float* x = (const float*)d_in[0];   // [B, 64]
    const float* t = (const float*)d_in[1];   // [64, 68]
    const float* c = (const float*)d_in[2];   // [64, 64]
    float* out = (float*)d_out;               // [B, 64]

    const int B = in_sizes[0] / N_SPLINES;    // 65536

    precompute_kernel<<<N_SPLINES, 256>>>(t, c);

    const size_t smemSz = (size_t)(32 * TH_STRIDE) * 4 + 48
                        + (size_t)(32 * C_STRIDE) * 16
                        + (size_t)(32 * BT_WORDS) * 4;          // ~105 KB
    cudaFuncSetAttribute(bspline_main_kernel,
                         cudaFuncAttributeMaxDynamicSharedMemorySize, (int)smemSz);

    dim3 grid(148, 2);
    bspline_main_kernel<<<grid, 1024, smemSz>>>(x, out, B);
}

// round 9
// speedup vs baseline: 1.2645x; 1.2645x over previous
#include <cuda_runtime.h>
#include <cstdint>
#include <math_constants.h>

#define N_SPLINES 64
#define C_DIM     64
#define T_DIM     68
#define NJ        67
#define NTH       (2*NJ)      // 134 raw thresholds per spline
#define NPF       (NTH + 1)   // 135 prefix polys (worst case)
#define NB        512         // buckets, width 1/64 over [-4,4)
#define NTHP      140         // padded distinct-threshold array

// Precomputed per-spline tables (dedup'd)
// g_th layout: [0] = -INF, [1..D] = distinct sorted thresholds, [D+1..139] = +INF
__device__ float   g_th[N_SPLINES][NTHP];
__device__ float4  g_C [N_SPLINES][NPF];     // Taylor coeffs of prefix poly m (0..D)
__device__ uint8_t g_bt[N_SPLINES][NB];      // bucket -> #{distinct th < edge_b}; bt[0]=0

// ---------------------------------------------------------------------------
// Precompute (fp64), level-parallel:
// reciprocals -> p1 -> p2 -> p3 (each entry built once) -> Q_j -> thresholds
// -> sort -> prefix polys -> parallel dedup -> Taylor-center -> buckets.
// ---------------------------------------------------------------------------
__device__ __forceinline__ double sinv(double den) {
    return den == 0.0 ? 0.0 : 1.0 / den;
}

__global__ void precompute_kernel(const float* __restrict__ t,
                                  const float* __restrict__ c) {
    const int s   = blockIdx.x;
    const int tid = threadIdx.x;

    __shared__ double st[T_DIM];
    __shared__ double sc[C_DIM];
    __shared__ double inv1[67], inv2[66], inv3[65];
    __shared__ double p1[66][2][2];
    __shared__ double p2[65][3][3];
    __shared__ double p3[64][4][4];
    __shared__ double qm[NJ][4];
    __shared__ float  thr[NTH];
    __shared__ float  sth[NTH];
    __shared__ int    sidx[NTH];
    __shared__ double sv[NTH][4];
    __shared__ float  dval[NTH];
    __shared__ int    dmap[NTH];
    __shared__ int    flg[NTH];
    __shared__ int    dcnt;

    if (tid < T_DIM) st[tid] = (double)t[s * T_DIM + tid];
    if (tid < C_DIM) sc[tid] = (double)c[s * C_DIM + tid];
    __syncthreads();

    // L0: reciprocal gaps (198 divisions spread over 256 threads)
    if (tid < 67) inv1[tid] = sinv(st[tid + 1] - st[tid]);
    else if (tid < 133) { int a = tid - 67; inv2[a] = sinv(st[a + 2] - st[a]); }
    else if (tid < 198) { int a = tid - 133; inv3[a] = sinv(st[a + 3] - st[a]); }
    __syncthreads();

    // L1: degree-1 basis pieces (66 entries)
    if (tid < 66) {
        int a = tid;
        p1[a][0][0] = -st[a] * inv1[a];       p1[a][0][1] = inv1[a];
        p1[a][1][0] = st[a + 2] * inv1[a + 1]; p1[a][1][1] = -inv1[a + 1];
    }
    __syncthreads();

    // L2: degree-2 basis pieces (65 entries)
    if (tid < 65) {
        int a = tid;
        double l0 = -st[a] * inv2[a],       l1 = inv2[a];
        double r0 = st[a + 3] * inv2[a + 1], r1 = -inv2[a + 1];
        double o[3][3];
#pragma unroll
        for (int jj = 0; jj < 3; ++jj)
#pragma unroll
            for (int d = 0; d < 3; ++d) o[jj][d] = 0.0;
#pragma unroll
        for (int jj = 0; jj < 2; ++jj)
#pragma unroll
            for (int d = 0; d < 2; ++d) {
                o[jj][d]     += l0 * p1[a][jj][d];
                o[jj][d + 1] += l1 * p1[a][jj][d];
            }
#pragma unroll
        for (int jj = 1; jj < 3; ++jj)
#pragma unroll
            for (int d = 0; d < 2; ++d) {
                o[jj][d]     += r0 * p1[a + 1][jj - 1][d];
                o[jj][d + 1] += r1 * p1[a + 1][jj - 1][d];
            }
#pragma unroll
        for (int jj = 0; jj < 3; ++jj)
#pragma unroll
            for (int d = 0; d < 3; ++d) p2[a][jj][d] = o[jj][d];
    }
    __syncthreads();

    // L3: degree-3 basis pieces (64 entries)
    if (tid < 64) {
        int i = tid;
        double l0 = -st[i] * inv3[i],       l1 = inv3[i];
        double r0 = st[i + 4] * inv3[i + 1], r1 = -inv3[i + 1];
        double o[4][4];
#pragma unroll
        for (int jj = 0; jj < 4; ++jj)
#pragma unroll
            for (int d = 0; d < 4; ++d) o[jj][d] = 0.0;
#pragma unroll
        for (int jj = 0; jj < 3; ++jj)
#pragma unroll
            for (int d = 0; d < 3; ++d) {
                o[jj][d]     += l0 * p2[i][jj][d];
                o[jj][d + 1] += l1 * p2[i][jj][d];
            }
#pragma unroll
        for (int jj = 1; jj < 4; ++jj)
#pragma unroll
            for (int d = 0; d < 3; ++d) {
                o[jj][d]     += r0 * p2[i + 1][jj - 1][d];
                o[jj][d + 1] += r1 * p2[i + 1][jj - 1][d];
            }
#pragma unroll
        for (int jj = 0; jj < 4; ++jj)
#pragma unroll
            for (int d = 0; d < 4; ++d) p3[i][jj][d] = o[jj][d];
    }
    __syncthreads();

    // A2: thread j combines pieces -> monomial Q_j
    if (tid < NJ) {
        int j = tid;
        double bb[4] = {0.0, 0.0, 0.0, 0.0};
        int ilo = (j - 3 < 0) ? 0 : j - 3;
        int ihi = (j < C_DIM - 1) ? j : C_DIM - 1;
        for (int i = ilo; i <= ihi; ++i) {
            int jj = j - i;
            double ci = sc[i];
#pragma unroll
            for (int d = 0; d < 4; ++d) bb[d] += ci * p3[i][jj][d];
        }
#pragma unroll
        for (int d = 0; d < 4; ++d) qm[j][d] = bb[d];
    }

    // B: raw thresholds
    if (tid < NTH) {
        if (tid < NJ) thr[tid] = t[s * T_DIM + tid];
        else {
            int j = tid - NJ;
            thr[tid] = fmaxf(t[s * T_DIM + j], t[s * T_DIM + j + 1]);
        }
    }
    __syncthreads();

    // C: rank sort (stable)
    if (tid < NTH) {
        float v = thr[tid];
        int r = 0;
        for (int i = 0; i < NTH; ++i) {
            float w = thr[i];
            r += (w < v) || (w == v && i < tid);
        }
        sth[r] = v;
        sidx[r] = tid;
    }
    __syncthreads();

    // D: signed pieces, inclusive fp64 scan
    if (tid < NTH) {
        int k = sidx[tid];
        int p = (k < NJ) ? k : k - NJ;
        double sgn = (k < NJ) ? 1.0 : -1.0;
#pragma unroll
        for (int d = 0; d < 4; ++d) sv[tid][d] = sgn * qm[p][d];
    }
    __syncthreads();
    for (int stp = 1; stp < NTH; stp <<= 1) {
        double tmp[4] = {0.0, 0.0, 0.0, 0.0};
        bool act = (tid < NTH) && (tid >= stp);
        if (act) {
#pragma unroll
            for (int d = 0; d < 4; ++d) tmp[d] = sv[tid - stp][d];
        }
        __syncthreads();
        if (act) {
#pragma unroll
            for (int d = 0; d < 4; ++d) sv[tid][d] += tmp[d];
        }
        __syncthreads();
    }

    // D2: PARALLEL dedup — keep prefix AFTER the last copy of each value.
    if (tid < NTH)
        flg[tid] = (tid == NTH - 1) || (sth[tid + 1] != sth[tid]);
    __syncthreads();
    // inclusive int scan of flg
    for (int stp = 1; stp < NTH; stp <<= 1) {
        int tmp = 0;
        bool act = (tid < NTH) && (tid >= stp);
        if (act) tmp = flg[tid - stp];
        __syncthreads();
        if (act) flg[tid] += tmp;
        __syncthreads();
    }
    if (tid < NTH) {
        bool last = (tid == NTH - 1) || (sth[tid + 1] != sth[tid]);
        if (last) {
            int r = flg[tid] - 1;
            dval[r] = sth[tid];
            dmap[r] = tid;
        }
    }
    if (tid == 0) dcnt = flg[NTH - 1];
    __syncthreads();
    const int D = dcnt;

    // E: Taylor-center prefix poly m (1..D) at dval[m-1]; zero elsewhere
    if (tid <= NTH) {
        int m = tid;
        float4 oc = make_float4(0.f, 0.f, 0.f, 0.f);
        if (m > 0 && m <= D) {
            double bb[4];
#pragma unroll
            for (int d = 0; d < 4; ++d) bb[d] = sv[dmap[m - 1]][d];
            double tc = (double)dval[m - 1];
#pragma unroll
            for (int pass = 0; pass < 3; ++pass)
#pragma unroll
                for (int d = 2; d >= 0; --d)
                    if (d >= pass) bb[d] += tc * bb[d + 1];
            oc = make_float4((float)bb[0], (float)bb[1], (float)bb[2], (float)bb[3]);
        }
        g_C[s][m] = oc;
    }
    // F: padded distinct thresholds
    if (tid < NTHP - 1)
        g_th[s][tid + 1] = (tid < D) ? dval[tid] : CUDART_INF_F;
    if (tid == 0) g_th[s][0] = -CUDART_INF_F;

    // G: bucket table bt[b] = #{distinct th < edge_b}; edge_0 = -INF
    for (int b = tid; b < NB; b += blockDim.x) {
        int cnt = 0;
        if (b > 0) {
            float edge = -4.0f + (float)b * (1.0f / 64.0f);   // exact in fp32
            for (int i = 0; i < D; ++i) cnt += (dval[i] < edge);
        }
        g_bt[s][b] = (uint8_t)cnt;
    }
}

// ---------------------------------------------------------------------------
// Main kernel: branchless bucket + 5 probes (v selected from probes, no
// reload); per-lane bad-bitmask; single cold fixup block after the row loop.
// ---------------------------------------------------------------------------
#define TH_STRIDE 141   // floats per spline (140 used), 141%32=13 coprime
#define C_STRIDE  137   // float4 per spline (135 used), odd
#define BT_WORDS  129   // words per spline bucket row (128 used), odd

extern __shared__ float dynsmem[];

__global__ __launch_bounds__(1024, 2)
void bspline_main_kernel(const float* __restrict__ x,
                         float* __restrict__ out, int B) {
    float*    sTh = dynsmem;                                  // 32*141 floats
    float4*   sC  = (float4*)(dynsmem + 32 * TH_STRIDE + 12); // 16B aligned
    uint32_t* sBt = (uint32_t*)(sC + 32 * C_STRIDE);          // 32*129 words

    const int tid   = threadIdx.x;
    const int sBase = blockIdx.y * 32;

    for (int i = tid; i < 32 * NTHP; i += 1024) {
        int sp = i / NTHP, k = i - sp * NTHP;
        sTh[sp * TH_STRIDE + k] = g_th[sBase + sp][k];
    }
    for (int i = tid; i < 32 * NPF; i += 1024) {
        int sp = i / NPF, k = i - sp * NPF;
        sC[sp * C_STRIDE + k] = g_C[sBase + sp][k];
    }
    for (int i = tid; i < 32 * (NB / 4); i += 1024) {
        int sp = i >> 7, k = i & 127;
        sBt[sp * BT_WORDS + k] = ((const uint32_t*)g_bt[sBase + sp])[k];
    }
    __syncthreads();

    const int lane = tid & 31;
    const int warp = tid >> 5;
    const float*   tbv = &sTh[lane * TH_STRIDE];   // sentinel-padded distinct th
    const float4*  cb  = &sC[lane * C_STRIDE];
    const uint8_t* btb = (const uint8_t*)&sBt[lane * BT_WORDS];
    const int col = sBase + lane;
    const int wstride = gridDim.x * 32;

    const int rstart = blockIdx.x * 32 + warp;
    int row = rstart;
    unsigned badmask = 0;
    int iter = 0;
    float xv = x[row * N_SPLINES + col];

    while (true) {
        const int  nrow = row + wstride;
        const bool more = (nrow < B);
        float xn = 0.0f;
        if (more) xn = x[nrow * N_SPLINES + col];          // prefetch next row

        int b = __float2int_rz(fmaf(xv, 64.0f, 256.0f));   // (x+4)*64
        b = min(max(b, 0), NB - 1);
        const int m0 = (int)btb[b];

        const float q0 = tbv[m0];
        const float q1 = tbv[m0 + 1];
        const float q2 = tbv[m0 + 2];
        const float q3 = tbv[m0 + 3];
        const float q4 = tbv[m0 + 4];

        const int cnt = (q1 <= xv) + (q2 <= xv) + (q3 <= xv);
        const bool bad = (q0 > xv) | (q4 <= xv);
        const int m = m0 + cnt;

        // v = tbv[m] selected from probes (no extra LDS)
        const float v = (cnt == 0) ? q0 : ((cnt == 1) ? q1 : ((cnt == 2) ? q2 : q3));
        const float  ctr = (m > 0) ? v : 0.0f;             // m=0 poly is zero
        const float4 cf  = cb[m];
        const float  u   = xv - ctr;
        out[row * N_SPLINES + col] =
            fmaf(fmaf(fmaf(cf.w, u, cf.z), u, cf.y), u, cf.x);

        badmask |= (bad ? 1u : 0u) << iter;

        if (!more) break;
        row = nrow; xv = xn; ++iter;
    }

    // Cold exact fixup for flagged rows
    if (badmask) {
        while (badmask) {
            const int i = __ffs(badmask) - 1;
            badmask &= badmask - 1;
            const int r = rstart + i * wstride;
            const float xw = x[r * N_SPLINES + col];

            int b = __float2int_rz(fmaf(xw, 64.0f, 256.0f));
            b = min(max(b, 0), NB - 1);
            int m = (int)btb[b];
            while (tbv[m] > xw) --m;          // -INF sentinel terminates
            while (tbv[m + 1] <= xw) ++m;     // +INF sentinels terminate

            const float  vv  = tbv[m];
            const float  ctr = (m > 0) ? vv : 0.0f;
            const float4 cf  = cb[m];
            const float  u   = xw - ctr;
            out[r * N_SPLINES + col] =
                fmaf(fmaf(fmaf(cf.w, u, cf.z), u, cf.y), u, cf.x);
        }
    }
}

// ---------------------------------------------------------------------------
extern "C" void kernel_launch(void* const* d_in, const int* in_sizes, int n_in,
                              void* d_out, int out_size) {
    const float* x = (const float*)d_in[0];   // [B, 64]
    const float* t = (const float*)d_in[1];   // [64, 68]
    const float* c = (const float*)d_in[2];   // [64, 64]
    float* out = (float*)d_out;               // [B, 64]

    const int B = in_sizes[0] / N_SPLINES;    // 65536

    precompute_kernel<<<N_SPLINES, 256>>>(t, c);

    const size_t smemSz = (size_t)(32 * TH_STRIDE) * 4 + 48
                        + (size_t)(32 * C_STRIDE) * 16
                        + (size_t)(32 * BT_WORDS) * 4;          // ~105 KB
    cudaFuncSetAttribute(bspline_main_kernel,
                         cudaFuncAttributeMaxDynamicSharedMemorySize, (int)smemSz);

    dim3 grid(148, 2);
    bspline_main_kernel<<<grid, 1024, smemSz>>>(x, out, B);
}

// round 10
// speedup vs baseline: 1.5251x; 1.2062x over previous
#include <cuda_runtime.h>
#include <cstdint>
#include <math_constants.h>

#define N_SPLINES 64
#define C_DIM     64
#define T_DIM     68
#define NJ        67
#define NTH       134          // raw thresholds
#define DMAX      68           // distinct thresholds are knot values => D <= 68
#define NTHD      75           // T array: [0]=-INF, [1..D], [D+1..74]=+INF
#define NPFD      71           // prefix polys m = 0..70 (m <= 68 used)
#define NB        512          // buckets, width 1/64 over [-4,4)

// Precomputed per-spline tables
__device__ float   g_th [N_SPLINES][NTHD];
__device__ float4  g_C  [N_SPLINES][NPFD];
__device__ uint8_t g_btT[NB][N_SPLINES];     // TRANSPOSED: [bucket][spline]

// ---------------------------------------------------------------------------
// Precompute (fp64), level-parallel; scan over <=68 distinct slots.
// ---------------------------------------------------------------------------
__device__ __forceinline__ double sinv(double den) {
    return den == 0.0 ? 0.0 : 1.0 / den;
}

__global__ void precompute_kernel(const float* __restrict__ t,
                                  const float* __restrict__ c) {
    const int s   = blockIdx.x;
    const int tid = threadIdx.x;

    __shared__ double st[T_DIM];
    __shared__ double sc[C_DIM];
    __shared__ double inv1[67], inv2[66], inv3[65];
    __shared__ double p1[66][2][2];
    __shared__ double p2[65][3][3];
    __shared__ double p3[64][4][4];
    __shared__ double qm[NJ][4];
    __shared__ float  thr[NTH];
    __shared__ float  sth[NTH];
    __shared__ int    sidx[NTH];
    __shared__ int    flg[NTH];
    __shared__ float  dval[NTH];
    __shared__ int    dmap[NTH];
    __shared__ double svd[DMAX][4];    // per-distinct-slot sums -> prefix

    if (tid < T_DIM) st[tid] = (double)t[s * T_DIM + tid];
    if (tid < C_DIM) sc[tid] = (double)c[s * C_DIM + tid];
    __syncthreads();

    // L0: reciprocal gaps
    if (tid < 67) inv1[tid] = sinv(st[tid + 1] - st[tid]);
    else if (tid < 133) { int a = tid - 67; inv2[a] = sinv(st[a + 2] - st[a]); }
    else if (tid < 198) { int a = tid - 133; inv3[a] = sinv(st[a + 3] - st[a]); }
    __syncthreads();

    // L1
    if (tid < 66) {
        int a = tid;
        p1[a][0][0] = -st[a] * inv1[a];        p1[a][0][1] = inv1[a];
        p1[a][1][0] = st[a + 2] * inv1[a + 1]; p1[a][1][1] = -inv1[a + 1];
    }
    __syncthreads();

    // L2
    if (tid < 65) {
        int a = tid;
        double l0 = -st[a] * inv2[a],        l1 = inv2[a];
        double r0 = st[a + 3] * inv2[a + 1], r1 = -inv2[a + 1];
        double o[3][3];
#pragma unroll
        for (int jj = 0; jj < 3; ++jj)
#pragma unroll
            for (int d = 0; d < 3; ++d) o[jj][d] = 0.0;
#pragma unroll
        for (int jj = 0; jj < 2; ++jj)
#pragma unroll
            for (int d = 0; d < 2; ++d) {
                o[jj][d]     += l0 * p1[a][jj][d];
                o[jj][d + 1] += l1 * p1[a][jj][d];
            }
#pragma unroll
        for (int jj = 1; jj < 3; ++jj)
#pragma unroll
            for (int d = 0; d < 2; ++d) {
                o[jj][d]     += r0 * p1[a + 1][jj - 1][d];
                o[jj][d + 1] += r1 * p1[a + 1][jj - 1][d];
            }
#pragma unroll
        for (int jj = 0; jj < 3; ++jj)
#pragma unroll
            for (int d = 0; d < 3; ++d) p2[a][jj][d] = o[jj][d];
    }
    __syncthreads();

    // L3
    if (tid < 64) {
        int i = tid;
        double l0 = -st[i] * inv3[i],        l1 = inv3[i];
        double r0 = st[i + 4] * inv3[i + 1], r1 = -inv3[i + 1];
        double o[4][4];
#pragma unroll
        for (int jj = 0; jj < 4; ++jj)
#pragma unroll
            for (int d = 0; d < 4; ++d) o[jj][d] = 0.0;
#pragma unroll
        for (int jj = 0; jj < 3; ++jj)
#pragma unroll
            for (int d = 0; d < 3; ++d) {
                o[jj][d]     += l0 * p2[i][jj][d];
                o[jj][d + 1] += l1 * p2[i][jj][d];
            }
#pragma unroll
        for (int jj = 1; jj < 4; ++jj)
#pragma unroll
            for (int d = 0; d < 3; ++d) {
                o[jj][d]     += r0 * p2[i + 1][jj - 1][d];
                o[jj][d + 1] += r1 * p2[i + 1][jj - 1][d];
            }
#pragma unroll
        for (int jj = 0; jj < 4; ++jj)
#pragma unroll
            for (int d = 0; d < 4; ++d) p3[i][jj][d] = o[jj][d];
    }
    __syncthreads();

    // Q_j monomial
    if (tid < NJ) {
        int j = tid;
        double bb[4] = {0.0, 0.0, 0.0, 0.0};
        int ilo = (j - 3 < 0) ? 0 : j - 3;
        int ihi = (j < C_DIM - 1) ? j : C_DIM - 1;
        for (int i = ilo; i <= ihi; ++i) {
            int jj = j - i;
            double ci = sc[i];
#pragma unroll
            for (int d = 0; d < 4; ++d) bb[d] += ci * p3[i][jj][d];
        }
#pragma unroll
        for (int d = 0; d < 4; ++d) qm[j][d] = bb[d];
    }

    // raw thresholds
    if (tid < NTH) {
        if (tid < NJ) thr[tid] = t[s * T_DIM + tid];
        else {
            int j = tid - NJ;
            thr[tid] = fmaxf(t[s * T_DIM + j], t[s * T_DIM + j + 1]);
        }
    }
    __syncthreads();

    // stable rank sort of raw thresholds
    if (tid < NTH) {
        float v = thr[tid];
        int r = 0;
        for (int i = 0; i < NTH; ++i) {
            float w = thr[i];
            r += (w < v) || (w == v && i < tid);
        }
        sth[r] = v;
        sidx[r] = tid;
    }
    __syncthreads();

    // dedup flags + int scan
    if (tid < NTH)
        flg[tid] = (tid == NTH - 1) || (sth[tid + 1] != sth[tid]);
    __syncthreads();
    for (int stp = 1; stp < NTH; stp <<= 1) {
        int tmp = 0;
        bool act = (tid < NTH) && (tid >= stp);
        if (act) tmp = flg[tid - stp];
        __syncthreads();
        if (act) flg[tid] += tmp;
        __syncthreads();
    }
    if (tid < NTH) {
        bool last = (tid == NTH - 1) || (sth[tid + 1] != sth[tid]);
        if (last) {
            int r = flg[tid] - 1;   // distinct slot index
            dval[r] = sth[tid];
            dmap[r] = tid;          // last raw position of this value
        }
    }
    __syncthreads();
    const int D = flg[NTH - 1];     // <= 68 (thresholds are knot values)

    // scatter raw signed pieces into distinct slots (<=3 per slot)
    if (tid < D) {
        int lo = (tid == 0) ? 0 : dmap[tid - 1] + 1;
        int hi = dmap[tid];
        double acc[4] = {0.0, 0.0, 0.0, 0.0};
        for (int i = lo; i <= hi; ++i) {
            int k = sidx[i];
            int p = (k < NJ) ? k : k - NJ;
            double sgn = (k < NJ) ? 1.0 : -1.0;
#pragma unroll
            for (int d = 0; d < 4; ++d) acc[d] += sgn * qm[p][d];
        }
#pragma unroll
        for (int d = 0; d < 4; ++d) svd[tid][d] = acc[d];
    }
    __syncthreads();

    // inclusive fp64 scan over D slots (7 steps)
    for (int stp = 1; stp < DMAX; stp <<= 1) {
        double tmp[4] = {0.0, 0.0, 0.0, 0.0};
        bool act = (tid < D) && (tid >= stp);
        if (act) {
#pragma unroll
            for (int d = 0; d < 4; ++d) tmp[d] = svd[tid - stp][d];
        }
        __syncthreads();
        if (act) {
#pragma unroll
            for (int d = 0; d < 4; ++d) svd[tid][d] += tmp[d];
        }
        __syncthreads();
    }

    // Taylor-center prefix poly m at dval[m-1]; zero-fill unused entries
    if (tid < NPFD) {
        int m = tid;
        float4 oc = make_float4(0.f, 0.f, 0.f, 0.f);
        if (m > 0 && m <= D) {
            double bb[4];
#pragma unroll
            for (int d = 0; d < 4; ++d) bb[d] = svd[m - 1][d];
            double tc = (double)dval[m - 1];
#pragma unroll
            for (int pass = 0; pass < 3; ++pass)
#pragma unroll
                for (int d = 2; d >= 0; --d)
                    if (d >= pass) bb[d] += tc * bb[d + 1];
            oc = make_float4((float)bb[0], (float)bb[1], (float)bb[2], (float)bb[3]);
        }
        g_C[s][m] = oc;
    }
    // padded distinct thresholds
    if (tid < NTHD) {
        float v;
        if (tid == 0)      v = -CUDART_INF_F;
        else if (tid <= D) v = dval[tid - 1];
        else               v = CUDART_INF_F;
        g_th[s][tid] = v;
    }
    // bucket table (transposed in gmem): btT[b][s] = #{distinct th < edge_b}
    for (int b = tid; b < NB; b += blockDim.x) {
        int cnt = 0;
        if (b > 0) {
            float edge = -4.0f + (float)b * (1.0f / 64.0f);   // exact in fp32
            for (int i = 0; i < D; ++i) cnt += (dval[i] < edge);
        }
        g_btT[b][s] = (uint8_t)cnt;
    }
}

// ---------------------------------------------------------------------------
// Main kernel: TRANSPOSED smem tables [index][lane] -> every per-lane-indexed
// LDS is bank-conflict-free. Bucket + 6 probes (window 5), badmask fixup.
// ---------------------------------------------------------------------------
extern __shared__ float dynsmem[];

__global__ __launch_bounds__(1024, 2)
void bspline_main_kernel(const float* __restrict__ x,
                         float* __restrict__ out, int B) {
    float*    sT = dynsmem;                         // [NTHD][32] floats  (9600 B)
    float4*   sC = (float4*)(dynsmem + NTHD * 32);  // [NPFD][32] float4  (36352 B)
    uint32_t* sB = (uint32_t*)(sC + NPFD * 32);     // [NB][32] bytes as words (16384 B)

    const int tid   = threadIdx.x;
    const int sBase = blockIdx.y * 32;

    for (int i = tid; i < NTHD * 32; i += 1024) {
        int k = i >> 5, sp = i & 31;
        sT[k * 32 + sp] = g_th[sBase + sp][k];
    }
    for (int i = tid; i < NPFD * 32; i += 1024) {
        int k = i >> 5, sp = i & 31;
        sC[k * 32 + sp] = g_C[sBase + sp][k];
    }
    for (int i = tid; i < NB * 8; i += 1024) {      // coalesced: g_btT rows
        int b = i >> 3, w = i & 7;
        sB[b * 8 + w] = ((const uint32_t*)&g_btT[b][sBase])[w];
    }
    __syncthreads();

    const int lane = tid & 31;
    const int warp = tid >> 5;
    const float*   tl  = sT + lane;                  // tl[m*32] = T[m], conflict-free
    const float4*  cl  = sC + lane;                  // cl[m*32] = coeffs, conflict-free
    const uint8_t* btl = (const uint8_t*)sB + lane;  // btl[b*32]
    const int col = sBase + lane;
    const int wstride = gridDim.x * 32;

    const int rstart = blockIdx.x * 32 + warp;
    int row = rstart;
    unsigned badmask = 0;
    int iter = 0;
    float xv = x[row * N_SPLINES + col];

    while (true) {
        const int  nrow = row + wstride;
        const bool more = (nrow < B);
        float xn = 0.0f;
        if (more) xn = x[nrow * N_SPLINES + col];          // prefetch next row

        int b = __float2int_rz(fmaf(xv, 64.0f, 256.0f));   // (x+4)*64
        b = min(max(b, 0), NB - 1);
        const int m0 = (int)btl[b * 32];

        const int mb = m0 * 32;
        const float q0 = tl[mb];
        const float q1 = tl[mb + 32];
        const float q2 = tl[mb + 64];
        const float q3 = tl[mb + 96];
        const float q4 = tl[mb + 128];
        const float q5 = tl[mb + 160];

        const int cnt = (q1 <= xv) + (q2 <= xv) + (q3 <= xv) + (q4 <= xv);
        const bool bad = (q0 > xv) | (q5 <= xv);
        const int m = m0 + cnt;

        const float v = (cnt == 0) ? q0
                      : (cnt == 1) ? q1
                      : (cnt == 2) ? q2
                      : (cnt == 3) ? q3 : q4;
        const float  ctr = (m > 0) ? v : 0.0f;             // m=0 poly is zero
        const float4 cf  = cl[m * 32];
        const float  u   = xv - ctr;
        out[row * N_SPLINES + col] =
            fmaf(fmaf(fmaf(cf.w, u, cf.z), u, cf.y), u, cf.x);

        badmask |= (bad ? 1u : 0u) << iter;

        if (!more) break;
        row = nrow; xv = xn; ++iter;
    }

    // Cold exact fixup for flagged rows
    if (badmask) {
        while (badmask) {
            const int i = __ffs(badmask) - 1;
            badmask &= badmask - 1;
            const int r = rstart + i * wstride;
            const float xw = x[r * N_SPLINES + col];

            int b = __float2int_rz(fmaf(xw, 64.0f, 256.0f));
            b = min(max(b, 0), NB - 1);
            int m = (int)btl[b * 32];
            while (tl[m * 32] > xw) --m;              // -INF sentinel terminates
            while (tl[(m + 1) * 32] <= xw) ++m;       // +INF sentinels terminate

            const float  vv  = tl[m * 32];
            const float  ctr = (m > 0) ? vv : 0.0f;
            const float4 cf  = cl[m * 32];
            const float  u   = xw - ctr;
            out[r * N_SPLINES + col] =
                fmaf(fmaf(fmaf(cf.w, u, cf.z), u, cf.y), u, cf.x);
        }
    }
}

// ---------------------------------------------------------------------------
extern "C" void kernel_launch(void* const* d_in, const int* in_sizes, int n_in,
                              void* d_out, int out_size) {
    const float* x = (const float*)d_in[0];   // [B, 64]
    const float* t = (const float*)d_in[1];   // [64, 68]
    const float* c = (const float*)d_in[2];   // [64, 64]
    float* out = (float*)d_out;               // [B, 64]

    const int B = in_sizes[0] / N_SPLINES;    // 65536

    precompute_kernel<<<N_SPLINES, 256>>>(t, c);

    const size_t smemSz = (size_t)(NTHD * 32) * 4      // sT   9600
                        + (size_t)(NPFD * 32) * 16     // sC  36352
                        + (size_t)NB * 32;             // sB  16384  => 62336 B
    cudaFuncSetAttribute(bspline_main_kernel,
                         cudaFuncAttributeMaxDynamicSharedMemorySize, (int)smemSz);

    dim3 grid(148, 2);
    bspline_main_kernel<<<grid, 1024, smemSz>>>(x, out, B);
}